// round 8
// baseline (speedup 1.0000x reference)
#include <cuda_runtime.h>
#include <cuda_fp16.h>
#include <stdint.h>
#include <math.h>

#define EPSV 1e-5f

// ---------------- scratch (device globals; no allocation allowed) ----------
__device__ __half2 g_ph[(size_t)8 * 16384 * 256]; // feat, [b][n][c/2] half2, 128MB
__device__ float g_Wt[512 * 512];                // BN-folded transposed conv weight [c][o]
__device__ float g_bias[512];                    // BN-folded bias
__device__ float g_c2[32];                       // ||codeword_k||^2
__device__ float g_enc[8 * 32 * 512];            // sum_n aw*feat accumulator
__device__ float g_awsum[8 * 32];                // sum_n aw
__device__ float g_ef[8 * 512];                  // encoding_feat
__device__ float g_gamma[8 * 512];               // sigmoid gate

__device__ __forceinline__ unsigned f2tf(float f) {
    unsigned r;
    asm("cvt.rna.tf32.f32 %0, %1;" : "=r"(r) : "f"(f));
    return r;
}
__device__ __forceinline__ float f2tff(float f) {
    return __uint_as_float(f2tf(f));
}

#define MMA_TF32(acc, a0, a1, a2, a3, b0, b1)                                  \
    asm volatile(                                                              \
        "mma.sync.aligned.m16n8k8.row.col.f32.tf32.tf32.f32 "                  \
        "{%0,%1,%2,%3}, {%4,%5,%6,%7}, {%8,%9}, {%0,%1,%2,%3};"                \
        : "+f"((acc)[0]), "+f"((acc)[1]), "+f"((acc)[2]), "+f"((acc)[3])       \
        : "r"(a0), "r"(a1), "r"(a2), "r"(a3), "r"(b0), "r"(b1))

#define MMA_F16(acc, a0, a1, a2, a3, b0, b1)                                   \
    asm volatile(                                                              \
        "mma.sync.aligned.m16n8k16.row.col.f32.f16.f16.f32 "                   \
        "{%0,%1,%2,%3}, {%4,%5,%6,%7}, {%8,%9}, {%0,%1,%2,%3};"                \
        : "+f"((acc)[0]), "+f"((acc)[1]), "+f"((acc)[2]), "+f"((acc)[3])       \
        : "r"(a0), "r"(a1), "r"(a2), "r"(a3), "r"(b0), "r"(b1))

// ---------------- K0: zero accumulators + fold BN2 + c2 --------------------
__global__ void k0_prep(const float* __restrict__ conv_w,
                        const float* __restrict__ cw,
                        const float* __restrict__ g2, const float* __restrict__ b2,
                        const float* __restrict__ m2, const float* __restrict__ v2) {
    int i = blockIdx.x * blockDim.x + threadIdx.x;
    if (i < 512 * 512) {
        int c = i >> 9;
        int o = i & 511;
        float scl = rsqrtf(v2[o] + EPSV) * g2[o];
        g_Wt[c * 512 + o] = conv_w[o * 512 + c] * scl;
        if (c == 0) g_bias[o] = b2[o] - m2[o] * scl;
    }
    if (i < 8 * 32 * 512) g_enc[i] = 0.f;
    if (i < 8 * 512) g_ef[i] = 0.f;
    if (i < 8 * 32) g_awsum[i] = 0.f;
    if (i < 32) {
        float s = 0.f;
        const float* r = cw + i * 512;
        for (int c = 0; c < 512; c++) s = fmaf(r[c], r[c], s);
        g_c2[i] = s;
    }
}

// dummy kernel: positions k1 at the ncu capture slot (4th launch)
__global__ void k_nop() {}

// ---------------- K1: fp16 mma.sync GEMM, 512 threads ----------------------
// BM=128 (n), BN=256 (o), BK=16. 16 warps (4m x 4o), warp tile 32x64.
#define K1_LDA2 136
#define K1_LDB2 264
#define K1_ASZ2 (8 * K1_LDA2)
#define K1_BSZ2 (8 * K1_LDB2)
#define K1_SMEM_BYTES (2 * (K1_ASZ2 + K1_BSZ2) * 4)   // 25600 B

__global__ __launch_bounds__(512) void k1_conv_f16(const float* __restrict__ x) {
    extern __shared__ __half2 smh[];
    __half2* Ab0 = smh;
    __half2* Ab1 = smh + K1_ASZ2;
    __half2* Bb0 = smh + 2 * K1_ASZ2;
    __half2* Bb1 = smh + 2 * K1_ASZ2 + K1_BSZ2;

    const int b = blockIdx.z;
    const int nBase = blockIdx.x * 128;
    const int oBase = blockIdx.y * 256;

    const int t = threadIdx.x;
    const int lane = t & 31;
    const int w = t >> 5;
    const int wm = w & 3;        // m warp 0..3
    const int wn = w >> 2;       // o warp 0..3

    const float* xb = x + (size_t)b * 512 * 16384;

    float acc[2][8][4];
#pragma unroll
    for (int mt = 0; mt < 2; mt++)
#pragma unroll
        for (int nt = 0; nt < 8; nt++)
#pragma unroll
            for (int r = 0; r < 4; r++) acc[mt][nt][r] = 0.f;

    // global-load indices: A handled by t<256 (1 unit), B by all 512 (1 unit)
    const bool aAct = (t < 256);
    const int ak = t >> 5;       // valid for t<256: 0..7 kp
    const int aq = t & 31;       // float4 col (n)
    const int bk = t >> 6;       // 0..7 kp
    const int bq = t & 63;       // float4 col (o)

    float4 raL, raH, rbL, rbH;

    if (aAct) {
        raL = *(const float4*)(xb + (size_t)(2 * ak)     * 16384 + nBase + aq * 4);
        raH = *(const float4*)(xb + (size_t)(2 * ak + 1) * 16384 + nBase + aq * 4);
    }
    rbL = *(const float4*)(g_Wt + (size_t)(2 * bk)     * 512 + oBase + bq * 4);
    rbH = *(const float4*)(g_Wt + (size_t)(2 * bk + 1) * 512 + oBase + bq * 4);

    {
        __half2 h[4];
        if (aAct) {
            h[0] = __floats2half2_rn(raL.x, raH.x);
            h[1] = __floats2half2_rn(raL.y, raH.y);
            h[2] = __floats2half2_rn(raL.z, raH.z);
            h[3] = __floats2half2_rn(raL.w, raH.w);
            *(uint4*)(Ab0 + ak * K1_LDA2 + aq * 4) = *(uint4*)h;
        }
        h[0] = __floats2half2_rn(rbL.x, rbH.x);
        h[1] = __floats2half2_rn(rbL.y, rbH.y);
        h[2] = __floats2half2_rn(rbL.z, rbH.z);
        h[3] = __floats2half2_rn(rbL.w, rbH.w);
        *(uint4*)(Bb0 + bk * K1_LDB2 + bq * 4) = *(uint4*)h;
    }
    __syncthreads();

    const int am  = wm * 32 + (lane >> 2);
    const int akp = lane & 3;
    const int bo  = wn * 64 + (lane >> 2);

    for (int kt = 0; kt < 32; kt++) {
        const int buf = kt & 1;
        const __half2* A = buf ? Ab1 : Ab0;
        const __half2* B = buf ? Bb1 : Bb0;

        if (kt < 31) {
            const int k0 = (kt + 1) * 16;
            if (aAct) {
                raL = *(const float4*)(xb + (size_t)(k0 + 2 * ak)     * 16384 + nBase + aq * 4);
                raH = *(const float4*)(xb + (size_t)(k0 + 2 * ak + 1) * 16384 + nBase + aq * 4);
            }
            rbL = *(const float4*)(g_Wt + (size_t)(k0 + 2 * bk)     * 512 + oBase + bq * 4);
            rbH = *(const float4*)(g_Wt + (size_t)(k0 + 2 * bk + 1) * 512 + oBase + bq * 4);
        }

        {
            unsigned af[2][4], bf[8][2];
#pragma unroll
            for (int mt = 0; mt < 2; mt++) {
                const unsigned* pa = (const unsigned*)(A + akp * K1_LDA2 + am + mt * 16);
                af[mt][0] = pa[0];
                af[mt][1] = pa[8];
                af[mt][2] = pa[4 * K1_LDA2];
                af[mt][3] = pa[4 * K1_LDA2 + 8];
            }
#pragma unroll
            for (int nt = 0; nt < 8; nt++) {
                const unsigned* pb = (const unsigned*)(B + akp * K1_LDB2 + bo + nt * 8);
                bf[nt][0] = pb[0];
                bf[nt][1] = pb[4 * K1_LDB2];
            }
#pragma unroll
            for (int mt = 0; mt < 2; mt++)
#pragma unroll
                for (int nt = 0; nt < 8; nt++)
                    MMA_F16(acc[mt][nt], af[mt][0], af[mt][1], af[mt][2], af[mt][3],
                            bf[nt][0], bf[nt][1]);
        }

        if (kt < 31) {
            __half2* An = buf ? Ab0 : Ab1;
            __half2* Bn = buf ? Bb0 : Bb1;
            __half2 h[4];
            if (aAct) {
                h[0] = __floats2half2_rn(raL.x, raH.x);
                h[1] = __floats2half2_rn(raL.y, raH.y);
                h[2] = __floats2half2_rn(raL.z, raH.z);
                h[3] = __floats2half2_rn(raL.w, raH.w);
                *(uint4*)(An + ak * K1_LDA2 + aq * 4) = *(uint4*)h;
            }
            h[0] = __floats2half2_rn(rbL.x, rbH.x);
            h[1] = __floats2half2_rn(rbL.y, rbH.y);
            h[2] = __floats2half2_rn(rbL.z, rbH.z);
            h[3] = __floats2half2_rn(rbL.w, rbH.w);
            *(uint4*)(Bn + bk * K1_LDB2 + bq * 4) = *(uint4*)h;
        }
        __syncthreads();
    }

    // epilogue: bias + relu -> g_ph half2
    const int rowBase = nBase + wm * 32 + (lane >> 2);
    const int colBase = oBase + wn * 64 + 2 * (lane & 3);
    const int colBase2 = colBase >> 1;
#pragma unroll
    for (int nt = 0; nt < 8; nt++) {
        const int col = colBase + nt * 8;
        float2 bj = *(const float2*)(g_bias + col);
#pragma unroll
        for (int mt = 0; mt < 2; mt++) {
            const int row = rowBase + mt * 16;
            __half2 h0 = __floats2half2_rn(fmaxf(acc[mt][nt][0] + bj.x, 0.f),
                                           fmaxf(acc[mt][nt][1] + bj.y, 0.f));
            __half2 h1 = __floats2half2_rn(fmaxf(acc[mt][nt][2] + bj.x, 0.f),
                                           fmaxf(acc[mt][nt][3] + bj.y, 0.f));
            g_ph[((size_t)b * 16384 + row) * 256 + colBase2 + nt * 4] = h0;
            g_ph[((size_t)b * 16384 + row + 8) * 256 + colBase2 + nt * 4] = h1;
        }
    }
}

// ---------------- K2: GEMM-based soft assignment + aggregation --------------
#define K2_LDF2 264                                   // half2 row stride
#define K2_LDW 34
#define K2_OFF_CW   (64 * K2_LDF2 * 4)
#define K2_OFF_XC   (K2_OFF_CW + 32 * K2_LDF2 * 4)
#define K2_OFF_AWS  (K2_OFF_XC + 64 * K2_LDW * 4)
#define K2_SMEM     (K2_OFF_AWS + 256 * 4)            // 111104 B

__global__ __launch_bounds__(256) void k2_enc(const float* __restrict__ codewords,
                                              const float* __restrict__ scale) {
    extern __shared__ char smem[];
    __half2* FEAT = (__half2*)smem;
    __half2* CW   = (__half2*)(smem + K2_OFF_CW);
    float*   XC   = (float*)(smem + K2_OFF_XC);
    float*   AWS  = (float*)(smem + K2_OFF_AWS);

    const int b = blockIdx.y;
    const int nBase = blockIdx.x * 64;
    const int t = threadIdx.x;
    const int lane = t & 31;
    const int w = t >> 5;

    {
        const uint4* src = (const uint4*)(g_ph + ((size_t)b * 16384 + nBase) * 256);
#pragma unroll
        for (int i = 0; i < 16; i++) {
            int idx = t + i * 256;
            int row = idx >> 6;
            int q = idx & 63;
            uint4 v = src[(size_t)row * 64 + q];
            *(uint4*)(FEAT + row * K2_LDF2 + q * 4) = v;
        }
    }
    {
#pragma unroll
        for (int i = 0; i < 8; i++) {
            int idx = t + i * 256;
            int row = idx >> 6;
            int q = idx & 63;
            const float* srcp = codewords + (size_t)row * 512 + q * 8;
            float4 v0 = *(const float4*)(srcp);
            float4 v1 = *(const float4*)(srcp + 4);
            __half2 h[4];
            h[0] = __floats2half2_rn(v0.x, v0.y);
            h[1] = __floats2half2_rn(v0.z, v0.w);
            h[2] = __floats2half2_rn(v1.x, v1.y);
            h[3] = __floats2half2_rn(v1.z, v1.w);
            *(uint4*)(CW + row * K2_LDF2 + q * 4) = *(uint4*)h;
        }
    }
    __syncthreads();

    // pass 1: xc[64][32] = feat @ cw^T (fp16 mma)
    {
        const int mi = w & 3;
        const int nb0 = (w >> 2) * 2;
        float xa[2][4] = {{0.f, 0.f, 0.f, 0.f}, {0.f, 0.f, 0.f, 0.f}};
        const __half2* A0 = FEAT + (mi * 16 + (lane >> 2)) * K2_LDF2 + (lane & 3);
        const __half2* B0 = CW + (lane >> 2) * K2_LDF2 + (lane & 3);
#pragma unroll 8
        for (int kk = 0; kk < 32; kk++) {
            const int ko = kk * 8;
            unsigned a0 = *(const unsigned*)(A0 + ko);
            unsigned a1 = *(const unsigned*)(A0 + ko + 8 * K2_LDF2);
            unsigned a2 = *(const unsigned*)(A0 + ko + 4);
            unsigned a3 = *(const unsigned*)(A0 + ko + 4 + 8 * K2_LDF2);
#pragma unroll
            for (int j = 0; j < 2; j++) {
                const __half2* Bp = B0 + (nb0 + j) * 8 * K2_LDF2 + ko;
                MMA_F16(xa[j], a0, a1, a2, a3,
                        *(const unsigned*)(Bp), *(const unsigned*)(Bp + 4));
            }
        }
        const int row = mi * 16 + (lane >> 2);
#pragma unroll
        for (int j = 0; j < 2; j++) {
            const int col = (nb0 + j) * 8 + 2 * (lane & 3);
            *(float2*)(XC + row * K2_LDW + col) = make_float2(xa[j][0], xa[j][1]);
            *(float2*)(XC + (row + 8) * K2_LDW + col) = make_float2(xa[j][2], xa[j][3]);
        }
    }
    __syncthreads();

    // softmax
    {
        float sc = scale[lane];
        float c2v = g_c2[lane];
        float awsum_l = 0.f;
#pragma unroll
        for (int rr = 0; rr < 8; rr++) {
            const int r = w * 8 + rr;
            const __half2* fr = FEAT + r * K2_LDF2;
            float s2 = 0.f;
#pragma unroll
            for (int q = 0; q < 8; q++) {
                float2 f = __half22float2(fr[lane + 32 * q]);
                s2 = fmaf(f.x, f.x, fmaf(f.y, f.y, s2));
            }
#pragma unroll
            for (int o = 16; o > 0; o >>= 1) s2 += __shfl_xor_sync(0xffffffffu, s2, o);
            float xcv = XC[r * K2_LDW + lane];
            float logit = sc * (s2 - 2.f * xcv + c2v);
            float m = logit;
#pragma unroll
            for (int o = 16; o > 0; o >>= 1) m = fmaxf(m, __shfl_xor_sync(0xffffffffu, m, o));
            float e = expf(logit - m);
            float ssum = e;
#pragma unroll
            for (int o = 16; o > 0; o >>= 1) ssum += __shfl_xor_sync(0xffffffffu, ssum, o);
            float aw = e / ssum;
            XC[r * K2_LDW + lane] = f2tff(aw);
            awsum_l += aw;
        }
        AWS[w * 32 + lane] = awsum_l;
    }
    __syncthreads();

    if (t < 32) {
        float sum = 0.f;
#pragma unroll
        for (int q = 0; q < 8; q++) sum += AWS[q * 32 + t];
        atomicAdd(&g_awsum[b * 32 + t], sum);
    }

    // pass 2: enc[32][512] += aw^T @ feat (tf32 mma, B from half)
    {
        const int cBase = w * 64;
        const int r = lane >> 2;
        const int krow = lane & 3;
        const bool hi = (r & 1);
        float acc2[2][8][4];
#pragma unroll
        for (int mb = 0; mb < 2; mb++)
#pragma unroll
            for (int nb = 0; nb < 8; nb++)
#pragma unroll
                for (int q = 0; q < 4; q++) acc2[mb][nb][q] = 0.f;

#pragma unroll
        for (int kk = 0; kk < 8; kk++) {
            const int ko = kk * 8;
            unsigned af[2][4];
#pragma unroll
            for (int mb = 0; mb < 2; mb++) {
                const float* ab = XC + (ko + krow) * K2_LDW + mb * 16 + r;
                af[mb][0] = __float_as_uint(ab[0]);
                af[mb][1] = __float_as_uint(ab[8]);
                af[mb][2] = __float_as_uint(ab[4 * K2_LDW]);
                af[mb][3] = __float_as_uint(ab[4 * K2_LDW + 8]);
            }
            const __half2* bb  = FEAT + (size_t)(ko + krow) * K2_LDF2 + (cBase >> 1) + (r >> 1);
            const __half2* bb4 = bb + 4 * K2_LDF2;
#pragma unroll
            for (int nb = 0; nb < 8; nb++) {
                __half2 h0 = bb[nb * 4];
                __half2 h1 = bb4[nb * 4];
                unsigned b0 = __float_as_uint(__half2float(hi ? __high2half(h0) : __low2half(h0)));
                unsigned b1 = __float_as_uint(__half2float(hi ? __high2half(h1) : __low2half(h1)));
#pragma unroll
                for (int mb = 0; mb < 2; mb++)
                    MMA_TF32(acc2[mb][nb], af[mb][0], af[mb][1], af[mb][2], af[mb][3],
                             b0, b1);
            }
        }

#pragma unroll
        for (int mb = 0; mb < 2; mb++) {
            const int code0 = mb * 16 + r;
            float* e0 = g_enc + ((size_t)b * 32 + code0) * 512;
            float* e1 = e0 + 8 * 512;
#pragma unroll
            for (int nb = 0; nb < 8; nb++) {
                const int col = cBase + nb * 8 + 2 * krow;
                atomicAdd(e0 + col,     acc2[mb][nb][0]);
                atomicAdd(e0 + col + 1, acc2[mb][nb][1]);
                atomicAdd(e1 + col,     acc2[mb][nb][2]);
                atomicAdd(e1 + col + 1, acc2[mb][nb][3]);
            }
        }
    }
}

// ---------------- K3a: BN1 + relu + partial mean over K ---------------------
__global__ void k3a_ef(const float* __restrict__ codewords,
                       const float* __restrict__ g1, const float* __restrict__ b1,
                       const float* __restrict__ m1, const float* __restrict__ v1) {
    int b = blockIdx.x;
    int kq = blockIdx.y;
    int c = threadIdx.x;
    float s = 0.f;
#pragma unroll
    for (int kk = 0; kk < 8; kk++) {
        int k = kq * 8 + kk;
        float e = g_enc[(b * 32 + k) * 512 + c] - g_awsum[b * 32 + k] * codewords[k * 512 + c];
        float inv = rsqrtf(v1[k] + EPSV) * g1[k];
        e = (e - m1[k]) * inv + b1[k];
        s += fmaxf(e, 0.f);
    }
    atomicAdd(&g_ef[b * 512 + c], s * (1.f / 32.f));
}

// ---------------- K3b: fc + sigmoid + ef output -----------------------------
__global__ void k3b_fc(const float* __restrict__ fc_w, const float* __restrict__ fc_b,
                       float* __restrict__ out_ef, int write_ef) {
    int b = blockIdx.x;
    int lane = threadIdx.x & 31;
    int wi = threadIdx.x >> 5;
    __shared__ float efs[512];
    efs[threadIdx.x] = g_ef[b * 512 + threadIdx.x];
    if (write_ef) out_ef[b * 512 + threadIdx.x] = efs[threadIdx.x];
    __syncthreads();

    for (int oo = 0; oo < 32; oo++) {
        int c = wi * 32 + oo;
        const float* wr = fc_w + (size_t)c * 512;
        float a = 0.f;
#pragma unroll
        for (int j = 0; j < 16; j++) {
            int i = lane + 32 * j;
            a = fmaf(efs[i], wr[i], a);
        }
#pragma unroll
        for (int o = 16; o > 0; o >>= 1) a += __shfl_xor_sync(0xffffffffu, a, o);
        if (lane == 0)
            g_gamma[b * 512 + c] = 1.f / (1.f + expf(-(a + fc_b[c])));
    }
}

// ---------------- K4: out = relu(x * (1 + gamma)) ---------------------------
__global__ __launch_bounds__(256) void k4_out(const float* __restrict__ x,
                                              float* __restrict__ out) {
    size_t i = (size_t)blockIdx.x * blockDim.x + threadIdx.x;
    float4 v = ((const float4*)x)[i];
    int bc = (int)(i >> 12);
    float g = 1.f + g_gamma[bc];
    float4 r;
    r.x = fmaxf(v.x * g, 0.f);
    r.y = fmaxf(v.y * g, 0.f);
    r.z = fmaxf(v.z * g, 0.f);
    r.w = fmaxf(v.w * g, 0.f);
    ((float4*)out)[i] = r;
}

// ---------------- launcher --------------------------------------------------
extern "C" void kernel_launch(void* const* d_in, const int* in_sizes, int n_in,
                              void* d_out, int out_size) {
    const float* x      = (const float*)d_in[0];
    const float* conv_w = (const float*)d_in[1];
    const float* bn2_g  = (const float*)d_in[2];
    const float* bn2_b  = (const float*)d_in[3];
    const float* bn2_m  = (const float*)d_in[4];
    const float* bn2_v  = (const float*)d_in[5];
    const float* cw     = (const float*)d_in[6];
    const float* scale  = (const float*)d_in[7];
    const float* bn1_g  = (const float*)d_in[8];
    const float* bn1_b  = (const float*)d_in[9];
    const float* bn1_m  = (const float*)d_in[10];
    const float* bn1_v  = (const float*)d_in[11];
    const float* fc_w   = (const float*)d_in[12];
    const float* fc_b   = (const float*)d_in[13];
    float* out = (float*)d_out;

    const long long OUT_MAIN = 67108864LL;
    long long off = (long long)out_size - OUT_MAIN;
    int write_ef = (off >= 4096) ? 1 : 0;
    if (off < 0) off = 0;

    k0_prep<<<1024, 256>>>(conv_w, cw, bn2_g, bn2_b, bn2_m, bn2_v);

    // position k1 at the (empirically) captured 4th launch slot
    k_nop<<<1, 32>>>();
    k_nop<<<1, 32>>>();

    dim3 g1(128, 2, 8);
    k1_conv_f16<<<g1, 512, K1_SMEM_BYTES>>>(x);

    cudaFuncSetAttribute(k2_enc, cudaFuncAttributeMaxDynamicSharedMemorySize,
                         K2_SMEM);
    dim3 g2(256, 8);
    k2_enc<<<g2, 256, K2_SMEM>>>(cw, scale);

    dim3 g3(8, 4);
    k3a_ef<<<g3, 512>>>(cw, bn1_g, bn1_b, bn1_m, bn1_v);
    k3b_fc<<<8, 512>>>(fc_w, fc_b, out, write_ef);

    k4_out<<<65536, 256>>>(x, out + off);
}

// round 9
// speedup vs baseline: 1.2062x; 1.2062x over previous
#include <cuda_runtime.h>
#include <cuda_fp16.h>
#include <stdint.h>
#include <math.h>

#define EPSV 1e-5f

// ---------------- scratch (device globals; no allocation allowed) ----------
__device__ __half  g_xh[(size_t)8 * 512 * 16384]; // x in fp16, [b][c][n], 128MB
__device__ __half2 g_ph[(size_t)8 * 16384 * 256]; // feat, [b][n][c/2] half2, 128MB
__device__ __half  g_Wh[512 * 512];               // BN-folded conv weight [c][o] fp16
__device__ float g_bias[512];
__device__ float g_c2[32];
__device__ float g_enc[8 * 32 * 512];
__device__ float g_awsum[8 * 32];
__device__ float g_ef[8 * 512];
__device__ float g_gamma[8 * 512];

__device__ __forceinline__ unsigned f2tf(float f) {
    unsigned r;
    asm("cvt.rna.tf32.f32 %0, %1;" : "=r"(r) : "f"(f));
    return r;
}
__device__ __forceinline__ float f2tff(float f) {
    return __uint_as_float(f2tf(f));
}
__device__ __forceinline__ uint32_t smem_u32(const void* p) {
    uint32_t a;
    asm("{ .reg .u64 t; cvta.to.shared.u64 t, %1; cvt.u32.u64 %0, t; }" : "=r"(a) : "l"(p));
    return a;
}

#define MMA_TF32(acc, a0, a1, a2, a3, b0, b1)                                  \
    asm volatile(                                                              \
        "mma.sync.aligned.m16n8k8.row.col.f32.tf32.tf32.f32 "                  \
        "{%0,%1,%2,%3}, {%4,%5,%6,%7}, {%8,%9}, {%0,%1,%2,%3};"                \
        : "+f"((acc)[0]), "+f"((acc)[1]), "+f"((acc)[2]), "+f"((acc)[3])       \
        : "r"(a0), "r"(a1), "r"(a2), "r"(a3), "r"(b0), "r"(b1))

#define MMA_F16(acc, a0, a1, a2, a3, b0, b1)                                   \
    asm volatile(                                                              \
        "mma.sync.aligned.m16n8k16.row.col.f32.f16.f16.f32 "                   \
        "{%0,%1,%2,%3}, {%4,%5,%6,%7}, {%8,%9}, {%0,%1,%2,%3};"                \
        : "+f"((acc)[0]), "+f"((acc)[1]), "+f"((acc)[2]), "+f"((acc)[3])       \
        : "r"(a0), "r"(a1), "r"(a2), "r"(a3), "r"(b0), "r"(b1))

#define CP_ASYNC16(dst, src) \
    asm volatile("cp.async.cg.shared.global [%0], [%1], 16;" :: "r"(dst), "l"(src))
#define CP_COMMIT() asm volatile("cp.async.commit_group;")
#define CP_WAIT2()  asm volatile("cp.async.wait_group 2;")

#define LDSM_X4_T(r0, r1, r2, r3, addr)                                        \
    asm volatile("ldmatrix.sync.aligned.m8n8.x4.trans.shared.b16 "             \
                 "{%0,%1,%2,%3}, [%4];"                                        \
                 : "=r"(r0), "=r"(r1), "=r"(r2), "=r"(r3) : "r"(addr))

// ---------------- K0: fold BN2 into half weights + zero accums + c2 --------
__global__ void k0_prep(const float* __restrict__ conv_w,
                        const float* __restrict__ cw,
                        const float* __restrict__ g2, const float* __restrict__ b2,
                        const float* __restrict__ m2, const float* __restrict__ v2) {
    int i = blockIdx.x * blockDim.x + threadIdx.x;
    if (i < 512 * 512) {
        int c = i >> 9;
        int o = i & 511;
        float scl = rsqrtf(v2[o] + EPSV) * g2[o];
        g_Wh[c * 512 + o] = __float2half(conv_w[o * 512 + c] * scl);
        if (c == 0) g_bias[o] = b2[o] - m2[o] * scl;
    }
    if (i < 8 * 32 * 512) g_enc[i] = 0.f;
    if (i < 8 * 512) g_ef[i] = 0.f;
    if (i < 8 * 32) g_awsum[i] = 0.f;
    if (i < 32) {
        float s = 0.f;
        const float* r = cw + i * 512;
        for (int c = 0; c < 512; c++) s = fmaf(r[c], r[c], s);
        g_c2[i] = s;
    }
}

// ---------------- K0x: convert x to fp16 ------------------------------------
__global__ __launch_bounds__(256) void k0x_cvt(const float* __restrict__ x) {
    size_t i = (size_t)blockIdx.x * 256 + threadIdx.x;   // float4 index (16.77M)
    float4 v = ((const float4*)x)[i];
    __half2 h0 = __floats2half2_rn(v.x, v.y);
    __half2 h1 = __floats2half2_rn(v.z, v.w);
    uint2 u;
    u.x = *(unsigned*)&h0;
    u.y = *(unsigned*)&h1;
    ((uint2*)g_xh)[i] = u;
}

__global__ void k_nop() {}

// ---------------- K1: fp16 mma + cp.async 4-stage + ldmatrix ---------------
// BM=64 (n), BN=256 (o), BK=16; 128 threads = 4 warps, each 64(m)x64(o).
// smem per stage: A [16 k][64 m] half rows padded to 144B; B [16 k][256 o] 528B.
#define K1_LDA_B 144
#define K1_LDB_B 528
#define K1_A_ST  (16 * K1_LDA_B)          // 2304
#define K1_B_ST  (16 * K1_LDB_B)          // 8448
#define K1_STAGE (K1_A_ST + K1_B_ST)      // 10752
#define K1_SMEM  (4 * K1_STAGE)           // 43008

__global__ void __launch_bounds__(128, 3) k1_conv_f16() {
    extern __shared__ char sm1[];
    const uint32_t sb = smem_u32(sm1);

    const int b = blockIdx.z;
    const int nBase = blockIdx.x * 64;
    const int oBase = blockIdx.y * 256;
    const int t = threadIdx.x;
    const int lane = t & 31;
    const int w = t >> 5;          // 0..3 = o-warp

    const __half* xb = g_xh + (size_t)b * 512 * 16384;

    // per-thread cp.async chunk coords
    const int arr = t >> 3, aru = t & 7;          // A: 128 chunks
    // B: 512 chunks, 4 per thread

    // prologue: fill stages 0..2
#pragma unroll
    for (int s = 0; s < 3; s++) {
        const int k0 = s * 16;
        const uint32_t as = sb + s * K1_STAGE;
        const uint32_t bs = as + K1_A_ST;
        CP_ASYNC16(as + arr * K1_LDA_B + aru * 16,
                   xb + (size_t)(k0 + arr) * 16384 + nBase + aru * 8);
#pragma unroll
        for (int j = 0; j < 4; j++) {
            int i = t + 128 * j;
            int r = i >> 5, u = i & 31;
            CP_ASYNC16(bs + r * K1_LDB_B + u * 16,
                       g_Wh + (size_t)(k0 + r) * 512 + oBase + u * 8);
        }
        CP_COMMIT();
    }

    float acc[4][8][4];
#pragma unroll
    for (int mt = 0; mt < 4; mt++)
#pragma unroll
        for (int nt = 0; nt < 8; nt++)
#pragma unroll
            for (int q = 0; q < 4; q++) acc[mt][nt][q] = 0.f;

    // ldmatrix lane addresses (byte offsets within stage)
    const int krowA = (lane & 7) + 8 * (lane >> 4);
    const int moffA = 8 * ((lane >> 3) & 1);
    const uint32_t aoff = (uint32_t)(krowA * K1_LDA_B + moffA * 2);
    const int krowB = (lane & 7) + 8 * ((lane >> 3) & 1);
    const int noffB = w * 64 + 8 * (lane >> 4);
    const uint32_t boff = (uint32_t)(krowB * K1_LDB_B + noffB * 2) + K1_A_ST;

    for (int kt = 0; kt < 32; kt++) {
        CP_WAIT2();
        __syncthreads();

        if (kt + 3 < 32) {
            const int s = (kt + 3) & 3;
            const int k0 = (kt + 3) * 16;
            const uint32_t as = sb + s * K1_STAGE;
            const uint32_t bs = as + K1_A_ST;
            CP_ASYNC16(as + arr * K1_LDA_B + aru * 16,
                       xb + (size_t)(k0 + arr) * 16384 + nBase + aru * 8);
#pragma unroll
            for (int j = 0; j < 4; j++) {
                int i = t + 128 * j;
                int r = i >> 5, u = i & 31;
                CP_ASYNC16(bs + r * K1_LDB_B + u * 16,
                           g_Wh + (size_t)(k0 + r) * 512 + oBase + u * 8);
            }
        }
        CP_COMMIT();   // commit every iter (possibly empty) to keep group count uniform

        const uint32_t stg = sb + (kt & 3) * K1_STAGE;

        unsigned af[4][4];
#pragma unroll
        for (int mt = 0; mt < 4; mt++)
            LDSM_X4_T(af[mt][0], af[mt][1], af[mt][2], af[mt][3],
                      stg + aoff + (uint32_t)(mt * 32));
        unsigned bf[8][2];
#pragma unroll
        for (int ntp = 0; ntp < 4; ntp++)
            LDSM_X4_T(bf[2 * ntp][0], bf[2 * ntp][1], bf[2 * ntp + 1][0], bf[2 * ntp + 1][1],
                      stg + boff + (uint32_t)(ntp * 32));

#pragma unroll
        for (int mt = 0; mt < 4; mt++)
#pragma unroll
            for (int nt = 0; nt < 8; nt++)
                MMA_F16(acc[mt][nt], af[mt][0], af[mt][1], af[mt][2], af[mt][3],
                        bf[nt][0], bf[nt][1]);
    }

    // epilogue: bias + relu -> g_ph half2
    const int rowBase = nBase + (lane >> 2);
    const int colBase = oBase + w * 64 + 2 * (lane & 3);
    const int colBase2 = colBase >> 1;
#pragma unroll
    for (int nt = 0; nt < 8; nt++) {
        const int col = colBase + nt * 8;
        float2 bj = *(const float2*)(g_bias + col);
#pragma unroll
        for (int mt = 0; mt < 4; mt++) {
            const int row = rowBase + mt * 16;
            __half2 h0 = __floats2half2_rn(fmaxf(acc[mt][nt][0] + bj.x, 0.f),
                                           fmaxf(acc[mt][nt][1] + bj.y, 0.f));
            __half2 h1 = __floats2half2_rn(fmaxf(acc[mt][nt][2] + bj.x, 0.f),
                                           fmaxf(acc[mt][nt][3] + bj.y, 0.f));
            g_ph[((size_t)b * 16384 + row) * 256 + colBase2 + nt * 4] = h0;
            g_ph[((size_t)b * 16384 + row + 8) * 256 + colBase2 + nt * 4] = h1;
        }
    }
}

// ---------------- K2: GEMM-based soft assignment + aggregation --------------
#define K2_LDF2 264
#define K2_LDW 34
#define K2_OFF_CW   (64 * K2_LDF2 * 4)
#define K2_OFF_XC   (K2_OFF_CW + 32 * K2_LDF2 * 4)
#define K2_OFF_AWS  (K2_OFF_XC + 64 * K2_LDW * 4)
#define K2_SMEM     (K2_OFF_AWS + 256 * 4)

__global__ __launch_bounds__(256) void k2_enc(const float* __restrict__ codewords,
                                              const float* __restrict__ scale) {
    extern __shared__ char smem[];
    __half2* FEAT = (__half2*)smem;
    __half2* CW   = (__half2*)(smem + K2_OFF_CW);
    float*   XC   = (float*)(smem + K2_OFF_XC);
    float*   AWS  = (float*)(smem + K2_OFF_AWS);

    const int b = blockIdx.y;
    const int nBase = blockIdx.x * 64;
    const int t = threadIdx.x;
    const int lane = t & 31;
    const int w = t >> 5;

    {
        const uint4* src = (const uint4*)(g_ph + ((size_t)b * 16384 + nBase) * 256);
#pragma unroll
        for (int i = 0; i < 16; i++) {
            int idx = t + i * 256;
            int row = idx >> 6;
            int q = idx & 63;
            uint4 v = src[(size_t)row * 64 + q];
            *(uint4*)(FEAT + row * K2_LDF2 + q * 4) = v;
        }
    }
    {
#pragma unroll
        for (int i = 0; i < 8; i++) {
            int idx = t + i * 256;
            int row = idx >> 6;
            int q = idx & 63;
            const float* srcp = codewords + (size_t)row * 512 + q * 8;
            float4 v0 = *(const float4*)(srcp);
            float4 v1 = *(const float4*)(srcp + 4);
            __half2 h[4];
            h[0] = __floats2half2_rn(v0.x, v0.y);
            h[1] = __floats2half2_rn(v0.z, v0.w);
            h[2] = __floats2half2_rn(v1.x, v1.y);
            h[3] = __floats2half2_rn(v1.z, v1.w);
            *(uint4*)(CW + row * K2_LDF2 + q * 4) = *(uint4*)h;
        }
    }
    __syncthreads();

    // pass 1: xc[64][32] = feat @ cw^T (fp16 mma)
    {
        const int mi = w & 3;
        const int nb0 = (w >> 2) * 2;
        float xa[2][4] = {{0.f, 0.f, 0.f, 0.f}, {0.f, 0.f, 0.f, 0.f}};
        const __half2* A0 = FEAT + (mi * 16 + (lane >> 2)) * K2_LDF2 + (lane & 3);
        const __half2* B0 = CW + (lane >> 2) * K2_LDF2 + (lane & 3);
#pragma unroll 8
        for (int kk = 0; kk < 32; kk++) {
            const int ko = kk * 8;
            unsigned a0 = *(const unsigned*)(A0 + ko);
            unsigned a1 = *(const unsigned*)(A0 + ko + 8 * K2_LDF2);
            unsigned a2 = *(const unsigned*)(A0 + ko + 4);
            unsigned a3 = *(const unsigned*)(A0 + ko + 4 + 8 * K2_LDF2);
#pragma unroll
            for (int j = 0; j < 2; j++) {
                const __half2* Bp = B0 + (nb0 + j) * 8 * K2_LDF2 + ko;
                MMA_F16(xa[j], a0, a1, a2, a3,
                        *(const unsigned*)(Bp), *(const unsigned*)(Bp + 4));
            }
        }
        const int row = mi * 16 + (lane >> 2);
#pragma unroll
        for (int j = 0; j < 2; j++) {
            const int col = (nb0 + j) * 8 + 2 * (lane & 3);
            *(float2*)(XC + row * K2_LDW + col) = make_float2(xa[j][0], xa[j][1]);
            *(float2*)(XC + (row + 8) * K2_LDW + col) = make_float2(xa[j][2], xa[j][3]);
        }
    }
    __syncthreads();

    // softmax
    {
        float sc = scale[lane];
        float c2v = g_c2[lane];
        float awsum_l = 0.f;
#pragma unroll
        for (int rr = 0; rr < 8; rr++) {
            const int r = w * 8 + rr;
            const __half2* fr = FEAT + r * K2_LDF2;
            float s2 = 0.f;
#pragma unroll
            for (int q = 0; q < 8; q++) {
                float2 f = __half22float2(fr[lane + 32 * q]);
                s2 = fmaf(f.x, f.x, fmaf(f.y, f.y, s2));
            }
#pragma unroll
            for (int o = 16; o > 0; o >>= 1) s2 += __shfl_xor_sync(0xffffffffu, s2, o);
            float xcv = XC[r * K2_LDW + lane];
            float logit = sc * (s2 - 2.f * xcv + c2v);
            float m = logit;
#pragma unroll
            for (int o = 16; o > 0; o >>= 1) m = fmaxf(m, __shfl_xor_sync(0xffffffffu, m, o));
            float e = expf(logit - m);
            float ssum = e;
#pragma unroll
            for (int o = 16; o > 0; o >>= 1) ssum += __shfl_xor_sync(0xffffffffu, ssum, o);
            float aw = e / ssum;
            XC[r * K2_LDW + lane] = f2tff(aw);
            awsum_l += aw;
        }
        AWS[w * 32 + lane] = awsum_l;
    }
    __syncthreads();

    if (t < 32) {
        float sum = 0.f;
#pragma unroll
        for (int q = 0; q < 8; q++) sum += AWS[q * 32 + t];
        atomicAdd(&g_awsum[b * 32 + t], sum);
    }

    // pass 2: enc[32][512] += aw^T @ feat (tf32 mma, B from half)
    {
        const int cBase = w * 64;
        const int r = lane >> 2;
        const int krow = lane & 3;
        const bool hi = (r & 1);
        float acc2[2][8][4];
#pragma unroll
        for (int mb = 0; mb < 2; mb++)
#pragma unroll
            for (int nb = 0; nb < 8; nb++)
#pragma unroll
                for (int q = 0; q < 4; q++) acc2[mb][nb][q] = 0.f;

#pragma unroll
        for (int kk = 0; kk < 8; kk++) {
            const int ko = kk * 8;
            unsigned af[2][4];
#pragma unroll
            for (int mb = 0; mb < 2; mb++) {
                const float* ab = XC + (ko + krow) * K2_LDW + mb * 16 + r;
                af[mb][0] = __float_as_uint(ab[0]);
                af[mb][1] = __float_as_uint(ab[8]);
                af[mb][2] = __float_as_uint(ab[4 * K2_LDW]);
                af[mb][3] = __float_as_uint(ab[4 * K2_LDW + 8]);
            }
            const __half2* bb  = FEAT + (size_t)(ko + krow) * K2_LDF2 + (cBase >> 1) + (r >> 1);
            const __half2* bb4 = bb + 4 * K2_LDF2;
#pragma unroll
            for (int nb = 0; nb < 8; nb++) {
                __half2 h0 = bb[nb * 4];
                __half2 h1 = bb4[nb * 4];
                unsigned b0 = __float_as_uint(__half2float(hi ? __high2half(h0) : __low2half(h0)));
                unsigned b1 = __float_as_uint(__half2float(hi ? __high2half(h1) : __low2half(h1)));
#pragma unroll
                for (int mb = 0; mb < 2; mb++)
                    MMA_TF32(acc2[mb][nb], af[mb][0], af[mb][1], af[mb][2], af[mb][3],
                             b0, b1);
            }
        }

#pragma unroll
        for (int mb = 0; mb < 2; mb++) {
            const int code0 = mb * 16 + r;
            float* e0 = g_enc + ((size_t)b * 32 + code0) * 512;
            float* e1 = e0 + 8 * 512;
#pragma unroll
            for (int nb = 0; nb < 8; nb++) {
                const int col = cBase + nb * 8 + 2 * krow;
                atomicAdd(e0 + col,     acc2[mb][nb][0]);
                atomicAdd(e0 + col + 1, acc2[mb][nb][1]);
                atomicAdd(e1 + col,     acc2[mb][nb][2]);
                atomicAdd(e1 + col + 1, acc2[mb][nb][3]);
            }
        }
    }
}

// ---------------- K3a: BN1 + relu + partial mean over K ---------------------
__global__ void k3a_ef(const float* __restrict__ codewords,
                       const float* __restrict__ g1, const float* __restrict__ b1,
                       const float* __restrict__ m1, const float* __restrict__ v1) {
    int b = blockIdx.x;
    int kq = blockIdx.y;
    int c = threadIdx.x;
    float s = 0.f;
#pragma unroll
    for (int kk = 0; kk < 8; kk++) {
        int k = kq * 8 + kk;
        float e = g_enc[(b * 32 + k) * 512 + c] - g_awsum[b * 32 + k] * codewords[k * 512 + c];
        float inv = rsqrtf(v1[k] + EPSV) * g1[k];
        e = (e - m1[k]) * inv + b1[k];
        s += fmaxf(e, 0.f);
    }
    atomicAdd(&g_ef[b * 512 + c], s * (1.f / 32.f));
}

// ---------------- K3b: fc + sigmoid + ef output -----------------------------
__global__ void k3b_fc(const float* __restrict__ fc_w, const float* __restrict__ fc_b,
                       float* __restrict__ out_ef, int write_ef) {
    int b = blockIdx.x;
    int lane = threadIdx.x & 31;
    int wi = threadIdx.x >> 5;
    __shared__ float efs[512];
    efs[threadIdx.x] = g_ef[b * 512 + threadIdx.x];
    if (write_ef) out_ef[b * 512 + threadIdx.x] = efs[threadIdx.x];
    __syncthreads();

    for (int oo = 0; oo < 32; oo++) {
        int c = wi * 32 + oo;
        const float* wr = fc_w + (size_t)c * 512;
        float a = 0.f;
#pragma unroll
        for (int j = 0; j < 16; j++) {
            int i = lane + 32 * j;
            a = fmaf(efs[i], wr[i], a);
        }
#pragma unroll
        for (int o = 16; o > 0; o >>= 1) a += __shfl_xor_sync(0xffffffffu, a, o);
        if (lane == 0)
            g_gamma[b * 512 + c] = 1.f / (1.f + expf(-(a + fc_b[c])));
    }
}

// ---------------- K4: out = relu(x * (1 + gamma)) ---------------------------
__global__ __launch_bounds__(256) void k4_out(const float* __restrict__ x,
                                              float* __restrict__ out) {
    size_t i = (size_t)blockIdx.x * blockDim.x + threadIdx.x;
    float4 v = ((const float4*)x)[i];
    int bc = (int)(i >> 12);
    float g = 1.f + g_gamma[bc];
    float4 r;
    r.x = fmaxf(v.x * g, 0.f);
    r.y = fmaxf(v.y * g, 0.f);
    r.z = fmaxf(v.z * g, 0.f);
    r.w = fmaxf(v.w * g, 0.f);
    ((float4*)out)[i] = r;
}

// ---------------- launcher --------------------------------------------------
extern "C" void kernel_launch(void* const* d_in, const int* in_sizes, int n_in,
                              void* d_out, int out_size) {
    const float* x      = (const float*)d_in[0];
    const float* conv_w = (const float*)d_in[1];
    const float* bn2_g  = (const float*)d_in[2];
    const float* bn2_b  = (const float*)d_in[3];
    const float* bn2_m  = (const float*)d_in[4];
    const float* bn2_v  = (const float*)d_in[5];
    const float* cw     = (const float*)d_in[6];
    const float* scale  = (const float*)d_in[7];
    const float* bn1_g  = (const float*)d_in[8];
    const float* bn1_b  = (const float*)d_in[9];
    const float* bn1_m  = (const float*)d_in[10];
    const float* bn1_v  = (const float*)d_in[11];
    const float* fc_w   = (const float*)d_in[12];
    const float* fc_b   = (const float*)d_in[13];
    float* out = (float*)d_out;

    const long long OUT_MAIN = 67108864LL;
    long long off = (long long)out_size - OUT_MAIN;
    int write_ef = (off >= 4096) ? 1 : 0;
    if (off < 0) off = 0;

    k0_prep<<<1024, 256>>>(conv_w, cw, bn2_g, bn2_b, bn2_m, bn2_v);
    k0x_cvt<<<65536, 256>>>(x);

    // keep k1 in the (empirically) captured 4th launch slot
    k_nop<<<1, 32>>>();

    dim3 g1(256, 2, 8);   // 64-row n-tiles, 2 o-tiles, batch
    k1_conv_f16<<<g1, 128, K1_SMEM>>>();

    cudaFuncSetAttribute(k2_enc, cudaFuncAttributeMaxDynamicSharedMemorySize,
                         K2_SMEM);
    dim3 g2(256, 8);
    k2_enc<<<g2, 256, K2_SMEM>>>(cw, scale);

    dim3 g3(8, 4);
    k3a_ef<<<g3, 512>>>(cw, bn1_g, bn1_b, bn1_m, bn1_v);
    k3b_fc<<<8, 512>>>(fc_w, fc_b, out, write_ef);

    k4_out<<<65536, 256>>>(x, out + off);
}

// round 10
// speedup vs baseline: 1.2719x; 1.0545x over previous
#include <cuda_runtime.h>
#include <cuda_fp16.h>
#include <stdint.h>
#include <math.h>

#define EPSV 1e-5f

// ---------------- scratch (device globals; no allocation allowed) ----------
__device__ __half  g_xh[(size_t)8 * 512 * 16384]; // x in fp16, [b][c][n], 128MB
__device__ __half2 g_ph[(size_t)8 * 16384 * 256]; // feat, [b][n][c/2] half2, 128MB
__device__ __half  g_Wh[512 * 512];               // BN-folded conv weight [c][o] fp16
__device__ __half2 g_cwh[32 * 256];               // codewords fp16, [k][c/2]
__device__ float g_bias[512];
__device__ float g_c2[32];
__device__ float g_enc[8 * 32 * 512];
__device__ float g_awsum[8 * 32];
__device__ float g_ef[8 * 512];
__device__ float g_gamma[8 * 512];

__device__ __forceinline__ uint32_t smem_u32(const void* p) {
    uint32_t a;
    asm("{ .reg .u64 t; cvta.to.shared.u64 t, %1; cvt.u32.u64 %0, t; }" : "=r"(a) : "l"(p));
    return a;
}

#define MMA_F16(acc, a0, a1, a2, a3, b0, b1)                                   \
    asm volatile(                                                              \
        "mma.sync.aligned.m16n8k16.row.col.f32.f16.f16.f32 "                   \
        "{%0,%1,%2,%3}, {%4,%5,%6,%7}, {%8,%9}, {%0,%1,%2,%3};"                \
        : "+f"((acc)[0]), "+f"((acc)[1]), "+f"((acc)[2]), "+f"((acc)[3])       \
        : "r"(a0), "r"(a1), "r"(a2), "r"(a3), "r"(b0), "r"(b1))

#define CP_ASYNC16(dst, src) \
    asm volatile("cp.async.cg.shared.global [%0], [%1], 16;" :: "r"(dst), "l"(src))
#define CP_COMMIT() asm volatile("cp.async.commit_group;")
#define CP_WAIT2()  asm volatile("cp.async.wait_group 2;")

#define LDSM_X4_T(r0, r1, r2, r3, addr)                                        \
    asm volatile("ldmatrix.sync.aligned.m8n8.x4.trans.shared.b16 "             \
                 "{%0,%1,%2,%3}, [%4];"                                        \
                 : "=r"(r0), "=r"(r1), "=r"(r2), "=r"(r3) : "r"(addr))

// ---------------- K0: fold BN2 into half weights + zero accums + c2 + cwh ---
__global__ void k0_prep(const float* __restrict__ conv_w,
                        const float* __restrict__ cw,
                        const float* __restrict__ g2, const float* __restrict__ b2,
                        const float* __restrict__ m2, const float* __restrict__ v2) {
    int i = blockIdx.x * blockDim.x + threadIdx.x;
    if (i < 512 * 512) {
        int c = i >> 9;
        int o = i & 511;
        float scl = rsqrtf(v2[o] + EPSV) * g2[o];
        g_Wh[c * 512 + o] = __float2half(conv_w[o * 512 + c] * scl);
        if (c == 0) g_bias[o] = b2[o] - m2[o] * scl;
    }
    if (i < 8 * 32 * 512) g_enc[i] = 0.f;
    if (i < 8 * 512) g_ef[i] = 0.f;
    if (i < 8 * 32) g_awsum[i] = 0.f;
    if (i < 32 * 256) {
        int k = i >> 8, cp = i & 255;
        g_cwh[i] = __floats2half2_rn(cw[k * 512 + 2 * cp], cw[k * 512 + 2 * cp + 1]);
    }
    if (i < 32) {
        float s = 0.f;
        const float* r = cw + i * 512;
        for (int c = 0; c < 512; c++) s = fmaf(r[c], r[c], s);
        g_c2[i] = s;
    }
}

// ---------------- K0x: convert x to fp16 ------------------------------------
__global__ __launch_bounds__(256) void k0x_cvt(const float* __restrict__ x) {
    size_t i = (size_t)blockIdx.x * 256 + threadIdx.x;
    float4 v = ((const float4*)x)[i];
    __half2 h0 = __floats2half2_rn(v.x, v.y);
    __half2 h1 = __floats2half2_rn(v.z, v.w);
    uint2 u;
    u.x = *(unsigned*)&h0;
    u.y = *(unsigned*)&h1;
    ((uint2*)g_xh)[i] = u;
}

// ---------------- K1: fp16 mma + cp.async 4-stage + ldmatrix (R8, frozen) ---
#define K1_LDA_B 144
#define K1_LDB_B 528
#define K1_A_ST  (16 * K1_LDA_B)
#define K1_B_ST  (16 * K1_LDB_B)
#define K1_STAGE (K1_A_ST + K1_B_ST)
#define K1_SMEM  (4 * K1_STAGE)

__global__ void __launch_bounds__(128, 3) k1_conv_f16() {
    extern __shared__ char sm1[];
    const uint32_t sb = smem_u32(sm1);

    const int b = blockIdx.z;
    const int nBase = blockIdx.x * 64;
    const int oBase = blockIdx.y * 256;
    const int t = threadIdx.x;
    const int lane = t & 31;
    const int w = t >> 5;

    const __half* xb = g_xh + (size_t)b * 512 * 16384;
    const int arr = t >> 3, aru = t & 7;

#pragma unroll
    for (int s = 0; s < 3; s++) {
        const int k0 = s * 16;
        const uint32_t as = sb + s * K1_STAGE;
        const uint32_t bs = as + K1_A_ST;
        CP_ASYNC16(as + arr * K1_LDA_B + aru * 16,
                   xb + (size_t)(k0 + arr) * 16384 + nBase + aru * 8);
#pragma unroll
        for (int j = 0; j < 4; j++) {
            int i = t + 128 * j;
            int r = i >> 5, u = i & 31;
            CP_ASYNC16(bs + r * K1_LDB_B + u * 16,
                       g_Wh + (size_t)(k0 + r) * 512 + oBase + u * 8);
        }
        CP_COMMIT();
    }

    float acc[4][8][4];
#pragma unroll
    for (int mt = 0; mt < 4; mt++)
#pragma unroll
        for (int nt = 0; nt < 8; nt++)
#pragma unroll
            for (int q = 0; q < 4; q++) acc[mt][nt][q] = 0.f;

    const int krowA = (lane & 7) + 8 * (lane >> 4);
    const int moffA = 8 * ((lane >> 3) & 1);
    const uint32_t aoff = (uint32_t)(krowA * K1_LDA_B + moffA * 2);
    const int krowB = (lane & 7) + 8 * ((lane >> 3) & 1);
    const int noffB = w * 64 + 8 * (lane >> 4);
    const uint32_t boff = (uint32_t)(krowB * K1_LDB_B + noffB * 2) + K1_A_ST;

    for (int kt = 0; kt < 32; kt++) {
        CP_WAIT2();
        __syncthreads();

        if (kt + 3 < 32) {
            const int s = (kt + 3) & 3;
            const int k0 = (kt + 3) * 16;
            const uint32_t as = sb + s * K1_STAGE;
            const uint32_t bs = as + K1_A_ST;
            CP_ASYNC16(as + arr * K1_LDA_B + aru * 16,
                       xb + (size_t)(k0 + arr) * 16384 + nBase + aru * 8);
#pragma unroll
            for (int j = 0; j < 4; j++) {
                int i = t + 128 * j;
                int r = i >> 5, u = i & 31;
                CP_ASYNC16(bs + r * K1_LDB_B + u * 16,
                           g_Wh + (size_t)(k0 + r) * 512 + oBase + u * 8);
            }
        }
        CP_COMMIT();

        const uint32_t stg = sb + (kt & 3) * K1_STAGE;

        unsigned af[4][4];
#pragma unroll
        for (int mt = 0; mt < 4; mt++)
            LDSM_X4_T(af[mt][0], af[mt][1], af[mt][2], af[mt][3],
                      stg + aoff + (uint32_t)(mt * 32));
        unsigned bf[8][2];
#pragma unroll
        for (int ntp = 0; ntp < 4; ntp++)
            LDSM_X4_T(bf[2 * ntp][0], bf[2 * ntp][1], bf[2 * ntp + 1][0], bf[2 * ntp + 1][1],
                      stg + boff + (uint32_t)(ntp * 32));

#pragma unroll
        for (int mt = 0; mt < 4; mt++)
#pragma unroll
            for (int nt = 0; nt < 8; nt++)
                MMA_F16(acc[mt][nt], af[mt][0], af[mt][1], af[mt][2], af[mt][3],
                        bf[nt][0], bf[nt][1]);
    }

    const int rowBase = nBase + (lane >> 2);
    const int colBase = oBase + w * 64 + 2 * (lane & 3);
    const int colBase2 = colBase >> 1;
#pragma unroll
    for (int nt = 0; nt < 8; nt++) {
        const int col = colBase + nt * 8;
        float2 bj = *(const float2*)(g_bias + col);
#pragma unroll
        for (int mt = 0; mt < 4; mt++) {
            const int row = rowBase + mt * 16;
            __half2 h0 = __floats2half2_rn(fmaxf(acc[mt][nt][0] + bj.x, 0.f),
                                           fmaxf(acc[mt][nt][1] + bj.y, 0.f));
            __half2 h1 = __floats2half2_rn(fmaxf(acc[mt][nt][2] + bj.x, 0.f),
                                           fmaxf(acc[mt][nt][3] + bj.y, 0.f));
            g_ph[((size_t)b * 16384 + row) * 256 + colBase2 + nt * 4] = h0;
            g_ph[((size_t)b * 16384 + row + 8) * 256 + colBase2 + nt * 4] = h1;
        }
    }
}

// ---------------- K2 v2: fp16 both passes, LDSM pass2, light softmax --------
// FEAT [64][260 half2], CW [32][260 half2]; LDF2=260 (words%32==4: LDSM-safe).
#define K2_LDF2 260
#define K2_OFF_CW   (64 * K2_LDF2 * 4)                 // 66560
#define K2_OFF_XC   (K2_OFF_CW + 32 * K2_LDF2 * 4)     // 99840
#define K2_OFF_X2P  (K2_OFF_XC + 64 * 33 * 4)          // 108288
#define K2_OFF_AWT  (K2_OFF_X2P + 256 * 4)             // 109312
#define K2_OFF_AWS  (K2_OFF_AWT + 32 * 72 * 2)         // 113920
#define K2_SMEM     (K2_OFF_AWS + 256 * 4)             // 114944

__global__ __launch_bounds__(256) void k2_enc(const float* __restrict__ scale) {
    extern __shared__ char smem[];
    __half2* FEAT = (__half2*)smem;
    __half2* CW   = (__half2*)(smem + K2_OFF_CW);
    float*   XC   = (float*)(smem + K2_OFF_XC);
    float*   X2P  = (float*)(smem + K2_OFF_X2P);
    __half*  AWT  = (__half*)(smem + K2_OFF_AWT);
    float*   AWS  = (float*)(smem + K2_OFF_AWS);
    const uint32_t featb = smem_u32(smem);

    const int b = blockIdx.y;
    const int nBase = blockIdx.x * 64;
    const int t = threadIdx.x;
    const int lane = t & 31;
    const int w = t >> 5;

    // ---- stage FEAT [64][256 half2] ----
    {
        const uint4* src = (const uint4*)(g_ph + ((size_t)b * 16384 + nBase) * 256);
#pragma unroll
        for (int i = 0; i < 16; i++) {
            int idx = t + i * 256;
            int row = idx >> 6;
            int q = idx & 63;
            uint4 v = src[(size_t)row * 64 + q];
            *(uint4*)(FEAT + row * K2_LDF2 + q * 4) = v;
        }
    }
    // ---- stage CW [32][256 half2] (pre-halved) ----
    {
        const uint4* src = (const uint4*)g_cwh;
#pragma unroll
        for (int i = 0; i < 8; i++) {
            int idx = t + i * 256;
            int row = idx >> 6;
            int q = idx & 63;
            uint4 v = src[row * 64 + q];
            *(uint4*)(CW + row * K2_LDF2 + q * 4) = v;
        }
    }
    __syncthreads();

    // ---- x2 partials: thread -> (row = t>>2, quarter q = t&3) ----
    {
        const int row = t >> 2;
        const int q = t & 3;
        const __half2* fr = FEAT + row * K2_LDF2 + q * 64;
        float s2 = 0.f;
#pragma unroll
        for (int j = 0; j < 64; j++) {
            float2 f = __half22float2(fr[(j + q) & 63]);
            s2 = fmaf(f.x, f.x, fmaf(f.y, f.y, s2));
        }
        X2P[t] = s2;   // X2P[row*4 + q]
    }

    // ---- pass 1: xc[64][32] = feat @ cw^T (fp16 mma) ----
    {
        const int mi = w & 3;
        const int nb0 = (w >> 2) * 2;
        float xa[2][4] = {{0.f, 0.f, 0.f, 0.f}, {0.f, 0.f, 0.f, 0.f}};
        const __half2* A0 = FEAT + (mi * 16 + (lane >> 2)) * K2_LDF2 + (lane & 3);
        const __half2* B0 = CW + (lane >> 2) * K2_LDF2 + (lane & 3);
#pragma unroll 8
        for (int kk = 0; kk < 32; kk++) {
            const int ko = kk * 8;
            unsigned a0 = *(const unsigned*)(A0 + ko);
            unsigned a1 = *(const unsigned*)(A0 + ko + 8 * K2_LDF2);
            unsigned a2 = *(const unsigned*)(A0 + ko + 4);
            unsigned a3 = *(const unsigned*)(A0 + ko + 4 + 8 * K2_LDF2);
#pragma unroll
            for (int j = 0; j < 2; j++) {
                const __half2* Bp = B0 + (nb0 + j) * 8 * K2_LDF2 + ko;
                MMA_F16(xa[j], a0, a1, a2, a3,
                        *(const unsigned*)(Bp), *(const unsigned*)(Bp + 4));
            }
        }
        const int row = mi * 16 + (lane >> 2);
#pragma unroll
        for (int j = 0; j < 2; j++) {
            const int col = (nb0 + j) * 8 + 2 * (lane & 3);
            XC[row * 33 + col]            = xa[j][0];
            XC[row * 33 + col + 1]        = xa[j][1];
            XC[(row + 8) * 33 + col]      = xa[j][2];
            XC[(row + 8) * 33 + col + 1]  = xa[j][3];
        }
    }
    __syncthreads();

    // ---- softmax: warp w -> rows w*8..w*8+7, lane = codeword ----
    {
        float sc = scale[lane];
        float c2v = g_c2[lane];
        float awsum_l = 0.f;
#pragma unroll
        for (int rr = 0; rr < 8; rr++) {
            const int r = w * 8 + rr;
            float s2 = X2P[r * 4] + X2P[r * 4 + 1] + X2P[r * 4 + 2] + X2P[r * 4 + 3];
            float xcv = XC[r * 33 + lane];
            float logit = sc * (s2 - 2.f * xcv + c2v);
            float m = logit;
#pragma unroll
            for (int o = 16; o > 0; o >>= 1) m = fmaxf(m, __shfl_xor_sync(0xffffffffu, m, o));
            float e = expf(logit - m);
            float ssum = e;
#pragma unroll
            for (int o = 16; o > 0; o >>= 1) ssum += __shfl_xor_sync(0xffffffffu, ssum, o);
            float aw = e / ssum;
            AWT[lane * 72 + r] = __float2half_rn(aw);   // transposed [k][n]
            awsum_l += aw;
        }
        AWS[w * 32 + lane] = awsum_l;
    }
    __syncthreads();

    if (t < 32) {
        float sum = 0.f;
#pragma unroll
        for (int q = 0; q < 8; q++) sum += AWS[q * 32 + t];
        atomicAdd(&g_awsum[b * 32 + t], sum);
    }

    // ---- pass 2: enc[32][512] += aw^T @ feat (fp16 mma, B via LDSM.trans) --
    {
        const int cBase = w * 64;                 // this warp's channel slice
        const unsigned* AWTw = (const unsigned*)AWT;   // 36 words per row
        const int gr = lane >> 2;
        const int kq = lane & 3;

        // LDSM lane address pieces (bytes)
        const int krowB = (lane & 7) + 8 * ((lane >> 3) & 1);
        const int coffB = cBase + 8 * (lane >> 4);

        float acc2[2][8][4];
#pragma unroll
        for (int mb = 0; mb < 2; mb++)
#pragma unroll
            for (int nb = 0; nb < 8; nb++)
#pragma unroll
                for (int q = 0; q < 4; q++) acc2[mb][nb][q] = 0.f;

#pragma unroll
        for (int kk = 0; kk < 4; kk++) {          // K = 64 n-rows, 16 per iter
            unsigned af[2][4];
#pragma unroll
            for (int mb = 0; mb < 2; mb++) {
                const int base = (mb * 16 + gr) * 36 + kq + kk * 8;
                af[mb][0] = AWTw[base];
                af[mb][1] = AWTw[base + 8 * 36];
                af[mb][2] = AWTw[base + 4];
                af[mb][3] = AWTw[base + 8 * 36 + 4];
            }
            unsigned bf[8][2];
            const uint32_t rowb = featb + (uint32_t)((kk * 16 + krowB) * (K2_LDF2 * 4));
#pragma unroll
            for (int ntp = 0; ntp < 4; ntp++)
                LDSM_X4_T(bf[2 * ntp][0], bf[2 * ntp][1],
                          bf[2 * ntp + 1][0], bf[2 * ntp + 1][1],
                          rowb + (uint32_t)((coffB + ntp * 16) * 2));
#pragma unroll
            for (int mb = 0; mb < 2; mb++)
#pragma unroll
                for (int nb = 0; nb < 8; nb++)
                    MMA_F16(acc2[mb][nb], af[mb][0], af[mb][1], af[mb][2], af[mb][3],
                            bf[nb][0], bf[nb][1]);
        }

#pragma unroll
        for (int mb = 0; mb < 2; mb++) {
            const int code0 = mb * 16 + gr;
            float* e0 = g_enc + ((size_t)b * 32 + code0) * 512;
            float* e1 = e0 + 8 * 512;
#pragma unroll
            for (int nb = 0; nb < 8; nb++) {
                const int col = cBase + nb * 8 + 2 * kq;
                atomicAdd(e0 + col,     acc2[mb][nb][0]);
                atomicAdd(e0 + col + 1, acc2[mb][nb][1]);
                atomicAdd(e1 + col,     acc2[mb][nb][2]);
                atomicAdd(e1 + col + 1, acc2[mb][nb][3]);
            }
        }
    }
}

// ---------------- K3a: BN1 + relu + partial mean over K ---------------------
__global__ void k3a_ef(const float* __restrict__ codewords,
                       const float* __restrict__ g1, const float* __restrict__ b1,
                       const float* __restrict__ m1, const float* __restrict__ v1) {
    int b = blockIdx.x;
    int kq = blockIdx.y;
    int c = threadIdx.x;
    float s = 0.f;
#pragma unroll
    for (int kk = 0; kk < 8; kk++) {
        int k = kq * 8 + kk;
        float e = g_enc[(b * 32 + k) * 512 + c] - g_awsum[b * 32 + k] * codewords[k * 512 + c];
        float inv = rsqrtf(v1[k] + EPSV) * g1[k];
        e = (e - m1[k]) * inv + b1[k];
        s += fmaxf(e, 0.f);
    }
    atomicAdd(&g_ef[b * 512 + c], s * (1.f / 32.f));
}

// ---------------- K3b: fc + sigmoid + ef output -----------------------------
__global__ void k3b_fc(const float* __restrict__ fc_w, const float* __restrict__ fc_b,
                       float* __restrict__ out_ef, int write_ef) {
    int b = blockIdx.x;
    int lane = threadIdx.x & 31;
    int wi = threadIdx.x >> 5;
    __shared__ float efs[512];
    efs[threadIdx.x] = g_ef[b * 512 + threadIdx.x];
    if (write_ef) out_ef[b * 512 + threadIdx.x] = efs[threadIdx.x];
    __syncthreads();

    for (int oo = 0; oo < 32; oo++) {
        int c = wi * 32 + oo;
        const float* wr = fc_w + (size_t)c * 512;
        float a = 0.f;
#pragma unroll
        for (int j = 0; j < 16; j++) {
            int i = lane + 32 * j;
            a = fmaf(efs[i], wr[i], a);
        }
#pragma unroll
        for (int o = 16; o > 0; o >>= 1) a += __shfl_xor_sync(0xffffffffu, a, o);
        if (lane == 0)
            g_gamma[b * 512 + c] = 1.f / (1.f + expf(-(a + fc_b[c])));
    }
}

// ---------------- K4: out = relu(x * (1 + gamma)) ---------------------------
__global__ __launch_bounds__(256) void k4_out(const float* __restrict__ x,
                                              float* __restrict__ out) {
    size_t i = (size_t)blockIdx.x * blockDim.x + threadIdx.x;
    float4 v = ((const float4*)x)[i];
    int bc = (int)(i >> 12);
    float g = 1.f + g_gamma[bc];
    float4 r;
    r.x = fmaxf(v.x * g, 0.f);
    r.y = fmaxf(v.y * g, 0.f);
    r.z = fmaxf(v.z * g, 0.f);
    r.w = fmaxf(v.w * g, 0.f);
    ((float4*)out)[i] = r;
}

// ---------------- launcher --------------------------------------------------
extern "C" void kernel_launch(void* const* d_in, const int* in_sizes, int n_in,
                              void* d_out, int out_size) {
    const float* x      = (const float*)d_in[0];
    const float* conv_w = (const float*)d_in[1];
    const float* bn2_g  = (const float*)d_in[2];
    const float* bn2_b  = (const float*)d_in[3];
    const float* bn2_m  = (const float*)d_in[4];
    const float* bn2_v  = (const float*)d_in[5];
    const float* cw     = (const float*)d_in[6];
    const float* scale  = (const float*)d_in[7];
    const float* bn1_g  = (const float*)d_in[8];
    const float* bn1_b  = (const float*)d_in[9];
    const float* bn1_m  = (const float*)d_in[10];
    const float* bn1_v  = (const float*)d_in[11];
    const float* fc_w   = (const float*)d_in[12];
    const float* fc_b   = (const float*)d_in[13];
    float* out = (float*)d_out;

    const long long OUT_MAIN = 67108864LL;
    long long off = (long long)out_size - OUT_MAIN;
    int write_ef = (off >= 4096) ? 1 : 0;
    if (off < 0) off = 0;

    k0_prep<<<1024, 256>>>(conv_w, cw, bn2_g, bn2_b, bn2_m, bn2_v);
    k0x_cvt<<<65536, 256>>>(x);

    dim3 g1(256, 2, 8);
    k1_conv_f16<<<g1, 128, K1_SMEM>>>();

    // k2 now sits in the ncu capture slot (4th launch)
    cudaFuncSetAttribute(k2_enc, cudaFuncAttributeMaxDynamicSharedMemorySize,
                         K2_SMEM);
    dim3 g2(256, 8);
    k2_enc<<<g2, 256, K2_SMEM>>>(scale);

    dim3 g3(8, 4);
    k3a_ef<<<g3, 512>>>(cw, bn1_g, bn1_b, bn1_m, bn1_v);
    k3b_fc<<<8, 512>>>(fc_w, fc_b, out, write_ef);

    k4_out<<<65536, 256>>>(x, out + off);
}

// round 11
// speedup vs baseline: 1.3364x; 1.0507x over previous
#include <cuda_runtime.h>
#include <cuda_fp16.h>
#include <stdint.h>
#include <math.h>

#define EPSV 1e-5f

// ---------------- scratch (device globals; no allocation allowed) ----------
__device__ __half  g_xh[(size_t)8 * 512 * 16384]; // x in fp16, [b][c][n], 128MB
__device__ __half2 g_ph[(size_t)8 * 16384 * 256]; // feat, [b][n][c/2] half2, 128MB
__device__ __half  g_Wh[512 * 512];               // BN-folded conv weight [c][o] fp16
__device__ __half2 g_cwh[32 * 256];               // codewords fp16, [k][c/2]
__device__ float g_bias[512];
__device__ float g_c2[32];
__device__ float g_enc[8 * 32 * 512];
__device__ float g_awsum[8 * 32];
__device__ float g_ef[8 * 512];
__device__ float g_gamma[8 * 512];

__device__ __forceinline__ uint32_t smem_u32(const void* p) {
    uint32_t a;
    asm("{ .reg .u64 t; cvta.to.shared.u64 t, %1; cvt.u32.u64 %0, t; }" : "=r"(a) : "l"(p));
    return a;
}

#define MMA_F16(acc, a0, a1, a2, a3, b0, b1)                                   \
    asm volatile(                                                              \
        "mma.sync.aligned.m16n8k16.row.col.f32.f16.f16.f32 "                   \
        "{%0,%1,%2,%3}, {%4,%5,%6,%7}, {%8,%9}, {%0,%1,%2,%3};"                \
        : "+f"((acc)[0]), "+f"((acc)[1]), "+f"((acc)[2]), "+f"((acc)[3])       \
        : "r"(a0), "r"(a1), "r"(a2), "r"(a3), "r"(b0), "r"(b1))

#define CP_ASYNC16(dst, src) \
    asm volatile("cp.async.cg.shared.global [%0], [%1], 16;" :: "r"(dst), "l"(src))
#define CP_COMMIT() asm volatile("cp.async.commit_group;")
#define CP_WAIT2()  asm volatile("cp.async.wait_group 2;")

#define LDSM_X4_T(r0, r1, r2, r3, addr)                                        \
    asm volatile("ldmatrix.sync.aligned.m8n8.x4.trans.shared.b16 "             \
                 "{%0,%1,%2,%3}, [%4];"                                        \
                 : "=r"(r0), "=r"(r1), "=r"(r2), "=r"(r3) : "r"(addr))

// ---------------- K0: fold BN2 into half weights + zero accums + c2 + cwh ---
__global__ void k0_prep(const float* __restrict__ conv_w,
                        const float* __restrict__ cw,
                        const float* __restrict__ g2, const float* __restrict__ b2,
                        const float* __restrict__ m2, const float* __restrict__ v2) {
    int i = blockIdx.x * blockDim.x + threadIdx.x;
    if (i < 512 * 512) {
        int c = i >> 9;
        int o = i & 511;
        float scl = rsqrtf(v2[o] + EPSV) * g2[o];
        g_Wh[c * 512 + o] = __float2half(conv_w[o * 512 + c] * scl);
        if (c == 0) g_bias[o] = b2[o] - m2[o] * scl;
    }
    if (i < 8 * 32 * 512) g_enc[i] = 0.f;
    if (i < 8 * 512) g_ef[i] = 0.f;
    if (i < 8 * 32) g_awsum[i] = 0.f;
    if (i < 32 * 256) {
        int k = i >> 8, cp = i & 255;
        g_cwh[i] = __floats2half2_rn(cw[k * 512 + 2 * cp], cw[k * 512 + 2 * cp + 1]);
    }
    if (i < 32) {
        float s = 0.f;
        const float* r = cw + i * 512;
        for (int c = 0; c < 512; c++) s = fmaf(r[c], r[c], s);
        g_c2[i] = s;
    }
}

// ---------------- K0x: convert x to fp16 ------------------------------------
__global__ __launch_bounds__(256) void k0x_cvt(const float* __restrict__ x) {
    size_t i = (size_t)blockIdx.x * 256 + threadIdx.x;
    float4 v = ((const float4*)x)[i];
    __half2 h0 = __floats2half2_rn(v.x, v.y);
    __half2 h1 = __floats2half2_rn(v.z, v.w);
    uint2 u;
    u.x = *(unsigned*)&h0;
    u.y = *(unsigned*)&h1;
    ((uint2*)g_xh)[i] = u;
}

// ---------------- K1: fp16 mma + cp.async 4-stage + ldmatrix (frozen) -------
#define K1_LDA_B 144
#define K1_LDB_B 528
#define K1_A_ST  (16 * K1_LDA_B)
#define K1_B_ST  (16 * K1_LDB_B)
#define K1_STAGE (K1_A_ST + K1_B_ST)
#define K1_SMEM  (4 * K1_STAGE)

__global__ void __launch_bounds__(128, 3) k1_conv_f16() {
    extern __shared__ char sm1[];
    const uint32_t sb = smem_u32(sm1);

    const int b = blockIdx.z;
    const int nBase = blockIdx.x * 64;
    const int oBase = blockIdx.y * 256;
    const int t = threadIdx.x;
    const int lane = t & 31;
    const int w = t >> 5;

    const __half* xb = g_xh + (size_t)b * 512 * 16384;
    const int arr = t >> 3, aru = t & 7;

#pragma unroll
    for (int s = 0; s < 3; s++) {
        const int k0 = s * 16;
        const uint32_t as = sb + s * K1_STAGE;
        const uint32_t bs = as + K1_A_ST;
        CP_ASYNC16(as + arr * K1_LDA_B + aru * 16,
                   xb + (size_t)(k0 + arr) * 16384 + nBase + aru * 8);
#pragma unroll
        for (int j = 0; j < 4; j++) {
            int i = t + 128 * j;
            int r = i >> 5, u = i & 31;
            CP_ASYNC16(bs + r * K1_LDB_B + u * 16,
                       g_Wh + (size_t)(k0 + r) * 512 + oBase + u * 8);
        }
        CP_COMMIT();
    }

    float acc[4][8][4];
#pragma unroll
    for (int mt = 0; mt < 4; mt++)
#pragma unroll
        for (int nt = 0; nt < 8; nt++)
#pragma unroll
            for (int q = 0; q < 4; q++) acc[mt][nt][q] = 0.f;

    const int krowA = (lane & 7) + 8 * (lane >> 4);
    const int moffA = 8 * ((lane >> 3) & 1);
    const uint32_t aoff = (uint32_t)(krowA * K1_LDA_B + moffA * 2);
    const int krowB = (lane & 7) + 8 * ((lane >> 3) & 1);
    const int noffB = w * 64 + 8 * (lane >> 4);
    const uint32_t boff = (uint32_t)(krowB * K1_LDB_B + noffB * 2) + K1_A_ST;

    for (int kt = 0; kt < 32; kt++) {
        CP_WAIT2();
        __syncthreads();

        if (kt + 3 < 32) {
            const int s = (kt + 3) & 3;
            const int k0 = (kt + 3) * 16;
            const uint32_t as = sb + s * K1_STAGE;
            const uint32_t bs = as + K1_A_ST;
            CP_ASYNC16(as + arr * K1_LDA_B + aru * 16,
                       xb + (size_t)(k0 + arr) * 16384 + nBase + aru * 8);
#pragma unroll
            for (int j = 0; j < 4; j++) {
                int i = t + 128 * j;
                int r = i >> 5, u = i & 31;
                CP_ASYNC16(bs + r * K1_LDB_B + u * 16,
                           g_Wh + (size_t)(k0 + r) * 512 + oBase + u * 8);
            }
        }
        CP_COMMIT();

        const uint32_t stg = sb + (kt & 3) * K1_STAGE;

        unsigned af[4][4];
#pragma unroll
        for (int mt = 0; mt < 4; mt++)
            LDSM_X4_T(af[mt][0], af[mt][1], af[mt][2], af[mt][3],
                      stg + aoff + (uint32_t)(mt * 32));
        unsigned bf[8][2];
#pragma unroll
        for (int ntp = 0; ntp < 4; ntp++)
            LDSM_X4_T(bf[2 * ntp][0], bf[2 * ntp][1], bf[2 * ntp + 1][0], bf[2 * ntp + 1][1],
                      stg + boff + (uint32_t)(ntp * 32));

#pragma unroll
        for (int mt = 0; mt < 4; mt++)
#pragma unroll
            for (int nt = 0; nt < 8; nt++)
                MMA_F16(acc[mt][nt], af[mt][0], af[mt][1], af[mt][2], af[mt][3],
                        bf[nt][0], bf[nt][1]);
    }

    const int rowBase = nBase + (lane >> 2);
    const int colBase = oBase + w * 64 + 2 * (lane & 3);
    const int colBase2 = colBase >> 1;
#pragma unroll
    for (int nt = 0; nt < 8; nt++) {
        const int col = colBase + nt * 8;
        float2 bj = *(const float2*)(g_bias + col);
#pragma unroll
        for (int mt = 0; mt < 4; mt++) {
            const int row = rowBase + mt * 16;
            __half2 h0 = __floats2half2_rn(fmaxf(acc[mt][nt][0] + bj.x, 0.f),
                                           fmaxf(acc[mt][nt][1] + bj.y, 0.f));
            __half2 h1 = __floats2half2_rn(fmaxf(acc[mt][nt][2] + bj.x, 0.f),
                                           fmaxf(acc[mt][nt][3] + bj.y, 0.f));
            g_ph[((size_t)b * 16384 + row) * 256 + colBase2 + nt * 4] = h0;
            g_ph[((size_t)b * 16384 + row + 8) * 256 + colBase2 + nt * 4] = h1;
        }
    }
}

// ---------------- K2 v2: fp16 both passes, LDSM pass2, light softmax --------
#define K2_LDF2 260
#define K2_OFF_CW   (64 * K2_LDF2 * 4)
#define K2_OFF_XC   (K2_OFF_CW + 32 * K2_LDF2 * 4)
#define K2_OFF_X2P  (K2_OFF_XC + 64 * 33 * 4)
#define K2_OFF_AWT  (K2_OFF_X2P + 256 * 4)
#define K2_OFF_AWS  (K2_OFF_AWT + 32 * 72 * 2)
#define K2_SMEM     (K2_OFF_AWS + 256 * 4)

__global__ void __launch_bounds__(256, 2) k2_enc(const float* __restrict__ scale) {
    extern __shared__ char smem[];
    __half2* FEAT = (__half2*)smem;
    __half2* CW   = (__half2*)(smem + K2_OFF_CW);
    float*   XC   = (float*)(smem + K2_OFF_XC);
    float*   X2P  = (float*)(smem + K2_OFF_X2P);
    __half*  AWT  = (__half*)(smem + K2_OFF_AWT);
    float*   AWS  = (float*)(smem + K2_OFF_AWS);
    const uint32_t featb = smem_u32(smem);

    const int b = blockIdx.y;
    const int nBase = blockIdx.x * 64;
    const int t = threadIdx.x;
    const int lane = t & 31;
    const int w = t >> 5;

    {
        const uint4* src = (const uint4*)(g_ph + ((size_t)b * 16384 + nBase) * 256);
#pragma unroll
        for (int i = 0; i < 16; i++) {
            int idx = t + i * 256;
            int row = idx >> 6;
            int q = idx & 63;
            uint4 v = src[(size_t)row * 64 + q];
            *(uint4*)(FEAT + row * K2_LDF2 + q * 4) = v;
        }
    }
    {
        const uint4* src = (const uint4*)g_cwh;
#pragma unroll
        for (int i = 0; i < 8; i++) {
            int idx = t + i * 256;
            int row = idx >> 6;
            int q = idx & 63;
            uint4 v = src[row * 64 + q];
            *(uint4*)(CW + row * K2_LDF2 + q * 4) = v;
        }
    }
    __syncthreads();

    {
        const int row = t >> 2;
        const int q = t & 3;
        const __half2* fr = FEAT + row * K2_LDF2 + q * 64;
        float s2 = 0.f;
#pragma unroll
        for (int j = 0; j < 64; j++) {
            float2 f = __half22float2(fr[(j + q) & 63]);
            s2 = fmaf(f.x, f.x, fmaf(f.y, f.y, s2));
        }
        X2P[t] = s2;
    }

    // pass 1: xc[64][32] = feat @ cw^T (fp16 mma)
    {
        const int mi = w & 3;
        const int nb0 = (w >> 2) * 2;
        float xa[2][4] = {{0.f, 0.f, 0.f, 0.f}, {0.f, 0.f, 0.f, 0.f}};
        const __half2* A0 = FEAT + (mi * 16 + (lane >> 2)) * K2_LDF2 + (lane & 3);
        const __half2* B0 = CW + (lane >> 2) * K2_LDF2 + (lane & 3);
#pragma unroll 8
        for (int kk = 0; kk < 32; kk++) {
            const int ko = kk * 8;
            unsigned a0 = *(const unsigned*)(A0 + ko);
            unsigned a1 = *(const unsigned*)(A0 + ko + 8 * K2_LDF2);
            unsigned a2 = *(const unsigned*)(A0 + ko + 4);
            unsigned a3 = *(const unsigned*)(A0 + ko + 4 + 8 * K2_LDF2);
#pragma unroll
            for (int j = 0; j < 2; j++) {
                const __half2* Bp = B0 + (nb0 + j) * 8 * K2_LDF2 + ko;
                MMA_F16(xa[j], a0, a1, a2, a3,
                        *(const unsigned*)(Bp), *(const unsigned*)(Bp + 4));
            }
        }
        const int row = mi * 16 + (lane >> 2);
#pragma unroll
        for (int j = 0; j < 2; j++) {
            const int col = (nb0 + j) * 8 + 2 * (lane & 3);
            XC[row * 33 + col]            = xa[j][0];
            XC[row * 33 + col + 1]        = xa[j][1];
            XC[(row + 8) * 33 + col]      = xa[j][2];
            XC[(row + 8) * 33 + col + 1]  = xa[j][3];
        }
    }
    __syncthreads();

    // softmax
    {
        float sc = scale[lane];
        float c2v = g_c2[lane];
        float awsum_l = 0.f;
#pragma unroll
        for (int rr = 0; rr < 8; rr++) {
            const int r = w * 8 + rr;
            float s2 = X2P[r * 4] + X2P[r * 4 + 1] + X2P[r * 4 + 2] + X2P[r * 4 + 3];
            float xcv = XC[r * 33 + lane];
            float logit = sc * (s2 - 2.f * xcv + c2v);
            float m = logit;
#pragma unroll
            for (int o = 16; o > 0; o >>= 1) m = fmaxf(m, __shfl_xor_sync(0xffffffffu, m, o));
            float e = expf(logit - m);
            float ssum = e;
#pragma unroll
            for (int o = 16; o > 0; o >>= 1) ssum += __shfl_xor_sync(0xffffffffu, ssum, o);
            float aw = e / ssum;
            AWT[lane * 72 + r] = __float2half_rn(aw);
            awsum_l += aw;
        }
        AWS[w * 32 + lane] = awsum_l;
    }
    __syncthreads();

    if (t < 32) {
        float sum = 0.f;
#pragma unroll
        for (int q = 0; q < 8; q++) sum += AWS[q * 32 + t];
        atomicAdd(&g_awsum[b * 32 + t], sum);
    }

    // pass 2: enc += aw^T @ feat (fp16 mma, B via LDSM.trans)
    {
        const int cBase = w * 64;
        const unsigned* AWTw = (const unsigned*)AWT;
        const int gr = lane >> 2;
        const int kq = lane & 3;

        const int krowB = (lane & 7) + 8 * ((lane >> 3) & 1);
        const int coffB = cBase + 8 * (lane >> 4);

        float acc2[2][8][4];
#pragma unroll
        for (int mb = 0; mb < 2; mb++)
#pragma unroll
            for (int nb = 0; nb < 8; nb++)
#pragma unroll
                for (int q = 0; q < 4; q++) acc2[mb][nb][q] = 0.f;

#pragma unroll
        for (int kk = 0; kk < 4; kk++) {
            unsigned af[2][4];
#pragma unroll
            for (int mb = 0; mb < 2; mb++) {
                const int base = (mb * 16 + gr) * 36 + kq + kk * 8;
                af[mb][0] = AWTw[base];
                af[mb][1] = AWTw[base + 8 * 36];
                af[mb][2] = AWTw[base + 4];
                af[mb][3] = AWTw[base + 8 * 36 + 4];
            }
            unsigned bf[8][2];
            const uint32_t rowb = featb + (uint32_t)((kk * 16 + krowB) * (K2_LDF2 * 4));
#pragma unroll
            for (int ntp = 0; ntp < 4; ntp++)
                LDSM_X4_T(bf[2 * ntp][0], bf[2 * ntp][1],
                          bf[2 * ntp + 1][0], bf[2 * ntp + 1][1],
                          rowb + (uint32_t)((coffB + ntp * 16) * 2));
#pragma unroll
            for (int mb = 0; mb < 2; mb++)
#pragma unroll
                for (int nb = 0; nb < 8; nb++)
                    MMA_F16(acc2[mb][nb], af[mb][0], af[mb][1], af[mb][2], af[mb][3],
                            bf[nb][0], bf[nb][1]);
        }

#pragma unroll
        for (int mb = 0; mb < 2; mb++) {
            const int code0 = mb * 16 + gr;
            float* e0 = g_enc + ((size_t)b * 32 + code0) * 512;
            float* e1 = e0 + 8 * 512;
#pragma unroll
            for (int nb = 0; nb < 8; nb++) {
                const int col = cBase + nb * 8 + 2 * kq;
                atomicAdd(e0 + col,     acc2[mb][nb][0]);
                atomicAdd(e0 + col + 1, acc2[mb][nb][1]);
                atomicAdd(e1 + col,     acc2[mb][nb][2]);
                atomicAdd(e1 + col + 1, acc2[mb][nb][3]);
            }
        }
    }
}

// ---------------- K3a: BN1 + relu + partial mean over K ---------------------
__global__ void k3a_ef(const float* __restrict__ codewords,
                       const float* __restrict__ g1, const float* __restrict__ b1,
                       const float* __restrict__ m1, const float* __restrict__ v1) {
    int b = blockIdx.x;
    int kq = blockIdx.y;
    int c = threadIdx.x;
    float s = 0.f;
#pragma unroll
    for (int kk = 0; kk < 8; kk++) {
        int k = kq * 8 + kk;
        float e = g_enc[(b * 32 + k) * 512 + c] - g_awsum[b * 32 + k] * codewords[k * 512 + c];
        float inv = rsqrtf(v1[k] + EPSV) * g1[k];
        e = (e - m1[k]) * inv + b1[k];
        s += fmaxf(e, 0.f);
    }
    atomicAdd(&g_ef[b * 512 + c], s * (1.f / 32.f));
}

// ---------------- K3b: fc + sigmoid + ef output -----------------------------
__global__ void k3b_fc(const float* __restrict__ fc_w, const float* __restrict__ fc_b,
                       float* __restrict__ out_ef, int write_ef) {
    int b = blockIdx.x;
    int lane = threadIdx.x & 31;
    int wi = threadIdx.x >> 5;
    __shared__ float efs[512];
    efs[threadIdx.x] = g_ef[b * 512 + threadIdx.x];
    if (write_ef) out_ef[b * 512 + threadIdx.x] = efs[threadIdx.x];
    __syncthreads();

    for (int oo = 0; oo < 32; oo++) {
        int c = wi * 32 + oo;
        const float* wr = fc_w + (size_t)c * 512;
        float a = 0.f;
#pragma unroll
        for (int j = 0; j < 16; j++) {
            int i = lane + 32 * j;
            a = fmaf(efs[i], wr[i], a);
        }
#pragma unroll
        for (int o = 16; o > 0; o >>= 1) a += __shfl_xor_sync(0xffffffffu, a, o);
        if (lane == 0)
            g_gamma[b * 512 + c] = 1.f / (1.f + expf(-(a + fc_b[c])));
    }
}

// ---------------- K4: out = relu(x * (1 + gamma)), x from fp16 --------------
__global__ __launch_bounds__(256) void k4_out(float* __restrict__ out) {
    size_t i = (size_t)blockIdx.x * blockDim.x + threadIdx.x;   // float4 index
    uint2 u = ((const uint2*)g_xh)[i];
    __half2 h0 = *(__half2*)&u.x;
    __half2 h1 = *(__half2*)&u.y;
    float2 f0 = __half22float2(h0);
    float2 f1 = __half22float2(h1);
    int bc = (int)(i >> 12);
    float g = 1.f + g_gamma[bc];
    float4 r;
    r.x = fmaxf(f0.x * g, 0.f);
    r.y = fmaxf(f0.y * g, 0.f);
    r.z = fmaxf(f1.x * g, 0.f);
    r.w = fmaxf(f1.y * g, 0.f);
    ((float4*)out)[i] = r;
}

// ---------------- launcher --------------------------------------------------
extern "C" void kernel_launch(void* const* d_in, const int* in_sizes, int n_in,
                              void* d_out, int out_size) {
    const float* x      = (const float*)d_in[0];
    const float* conv_w = (const float*)d_in[1];
    const float* bn2_g  = (const float*)d_in[2];
    const float* bn2_b  = (const float*)d_in[3];
    const float* bn2_m  = (const float*)d_in[4];
    const float* bn2_v  = (const float*)d_in[5];
    const float* cw     = (const float*)d_in[6];
    const float* scale  = (const float*)d_in[7];
    const float* bn1_g  = (const float*)d_in[8];
    const float* bn1_b  = (const float*)d_in[9];
    const float* bn1_m  = (const float*)d_in[10];
    const float* bn1_v  = (const float*)d_in[11];
    const float* fc_w   = (const float*)d_in[12];
    const float* fc_b   = (const float*)d_in[13];
    float* out = (float*)d_out;

    const long long OUT_MAIN = 67108864LL;
    long long off = (long long)out_size - OUT_MAIN;
    int write_ef = (off >= 4096) ? 1 : 0;
    if (off < 0) off = 0;

    k0_prep<<<1024, 256>>>(conv_w, cw, bn2_g, bn2_b, bn2_m, bn2_v);
    k0x_cvt<<<65536, 256>>>(x);

    dim3 g1(256, 2, 8);
    k1_conv_f16<<<g1, 128, K1_SMEM>>>();

    // k2 in the ncu capture slot (4th launch); request max smem carveout + 2 CTAs
    cudaFuncSetAttribute(k2_enc, cudaFuncAttributeMaxDynamicSharedMemorySize,
                         K2_SMEM);
    cudaFuncSetAttribute(k2_enc, cudaFuncAttributePreferredSharedMemoryCarveout,
                         100);
    dim3 g2(256, 8);
    k2_enc<<<g2, 256, K2_SMEM>>>(scale);

    dim3 g3(8, 4);
    k3a_ef<<<g3, 512>>>(cw, bn1_g, bn1_b, bn1_m, bn1_v);
    k3b_fc<<<8, 512>>>(fc_w, fc_b, out, write_ef);

    k4_out<<<65536, 256>>>(out + off);
}